// round 3
// baseline (speedup 1.0000x reference)
#include <cuda_runtime.h>

// FrameLogLikelihood: segment-mean over [2048*2001, 16] fp32.
// Per sequence (2001 rows): rows 0..999     -> seg r%3          (counts 334,333,333)
//                           row 1000        -> dropped
//                           rows 1001..2000 -> seg 3+(r-1001)%3 (counts 334,333,333)
// Output [2048, 96]: out[seq, seg*16+m] = mean.
//
// One block per (sequence, half). Half = 1000 contiguous rows = 64 KB.
// 384 threads: m4 = t&3 selects a float4 of the 16-float row, rg = t>>2 in [0,96).
// Thread accumulates rows q = rg + 96*i; 96 % 3 == 0 so this thread's segment
// (rg % 3) is constant -> single static float4 accumulator (stays in registers).
// Warp = 8 consecutive rows => fully coalesced 512B per LDG.128 wave.
// First 10 iterations are unconditional (rg+864 <= 959 < 1000) so ptxas can
// front-batch the LDGs (high MLP); only the 11th row is predicated (rg < 40).

#define THREADS 384

__global__ __launch_bounds__(THREADS)
void seg_mean_kernel(const float* __restrict__ in, float* __restrict__ out) {
    __shared__ float4 smem[96][4];   // [rg][m4], each slot written by exactly one thread

    const int t    = threadIdx.x;
    const int m4   = t & 3;          // which float4 of the 16-float row
    const int rg   = t >> 2;         // 0..95 row-group; seg = rg % 3 (constant per thread)
    const int seq  = blockIdx.x >> 1;
    const int half = blockIdx.x & 1; // 0 = rows [0,1000), 1 = rows [1001,2001)

    // Row base of this half; units of float4 (4 float4 per 16-float row)
    const float4* __restrict__ base = reinterpret_cast<const float4*>(in)
        + ((size_t)seq * 2001 + (size_t)half * 1001) * 4;

    const float4* __restrict__ p = base + (size_t)rg * 4 + m4;

    float4 acc = make_float4(0.f, 0.f, 0.f, 0.f);

    // 10 unconditional rows: q = rg + 96*i, max = 95 + 864 = 959 < 1000.
    #pragma unroll
    for (int i = 0; i < 10; ++i) {
        float4 v = p[(size_t)(96 * 4) * i];
        acc.x += v.x;
        acc.y += v.y;
        acc.z += v.z;
        acc.w += v.w;
    }
    // Predicated tail: q = rg + 960, valid iff rg < 40.
    if (rg < 40) {
        float4 v = p[(size_t)(96 * 4) * 10];
        acc.x += v.x;
        acc.y += v.y;
        acc.z += v.z;
        acc.w += v.w;
    }

    smem[rg][m4] = acc;
    __syncthreads();

    // 48 output elements per block: (local seg s in 0..2) x (feature m in 0..15).
    // Sum the 32 row-groups with rg % 3 == s.
    if (t < 48) {
        const int s = t >> 4;    // 0..2
        const int m = t & 15;    // 0..15
        const float* sf = reinterpret_cast<const float*>(smem);  // 96*16 floats
        float sum = 0.f;
        #pragma unroll
        for (int k = 0; k < 32; ++k) {
            sum += sf[(s + 3 * k) * 16 + m];
        }
        const float scale = (s == 0) ? (1.0f / 334.0f) : (1.0f / 333.0f);
        out[(size_t)seq * 96 + (size_t)(half * 3 + s) * 16 + m] = sum * scale;
    }
}

extern "C" void kernel_launch(void* const* d_in, const int* in_sizes, int n_in,
                              void* d_out, int out_size) {
    const float* in = (const float*)d_in[0];
    float* out = (float*)d_out;
    seg_mean_kernel<<<4096, THREADS>>>(in, out);
}

// round 5
// speedup vs baseline: 1.0322x; 1.0322x over previous
#include <cuda_runtime.h>

// FrameLogLikelihood: segment-mean over [2048*2001, 16] fp32.
// Per sequence (2001 rows): rows 0..999     -> seg r%3          (counts 334,333,333)
//                           row 1000        -> dropped
//                           rows 1001..2000 -> seg 3+(r-1001)%3 (counts 334,333,333)
// Output [2048, 96]: out[seq, seg*16+m] = mean.
//
// One block per (sequence, half). Half = 1000 contiguous rows = 64 KB.
// 480 threads: m4 = t&3 selects a float4 of the 16-float row, rg = t>>2 in [0,120).
// Thread accumulates rows q = rg + 120*i; 120 % 3 == 0 so this thread's segment
// (rg % 3) is constant -> single static float4 accumulator in registers.
// Warp = 8 consecutive rows => fully coalesced 512B per LDG.128 wave.
// 8 unconditional iterations (rg+840 <= 959 < 1000), tail q=rg+960 iff rg<40.
//
// Block-shape choice is wave-quantization driven: 480 threads -> occ 4 ->
// n_conc = 148*4 = 592 -> 4096/592 = 6.92 waves (1.2% quantization loss),
// vs 7.7% loss at 384 threads / occ 5.

#define THREADS 480
#define RG      120   // row-groups per block (THREADS/4), multiple of 3

__global__ __launch_bounds__(THREADS, 4)
void seg_mean_kernel(const float* __restrict__ in, float* __restrict__ out) {
    __shared__ float4 smem[RG][4];   // [rg][m4], each slot written by exactly one thread

    const int t    = threadIdx.x;
    const int m4   = t & 3;          // which float4 of the 16-float row
    const int rg   = t >> 2;         // 0..119 row-group; seg = rg % 3 (constant per thread)
    const int seq  = blockIdx.x >> 1;
    const int half = blockIdx.x & 1; // 0 = rows [0,1000), 1 = rows [1001,2001)

    // Row base of this half; units of float4 (4 float4 per 16-float row)
    const float4* __restrict__ base = reinterpret_cast<const float4*>(in)
        + ((size_t)seq * 2001 + (size_t)half * 1001) * 4;

    const float4* __restrict__ p = base + (size_t)rg * 4 + m4;

    float4 acc = make_float4(0.f, 0.f, 0.f, 0.f);

    // 8 unconditional rows: q = rg + 120*i, max = 119 + 840 = 959 < 1000.
    #pragma unroll
    for (int i = 0; i < 8; ++i) {
        float4 v = p[(size_t)(RG * 4) * i];
        acc.x += v.x;
        acc.y += v.y;
        acc.z += v.z;
        acc.w += v.w;
    }
    // Predicated tail: q = rg + 960, valid iff rg < 40.
    if (rg < 40) {
        float4 v = p[(size_t)(RG * 4) * 8];
        acc.x += v.x;
        acc.y += v.y;
        acc.z += v.z;
        acc.w += v.w;
    }

    smem[rg][m4] = acc;
    __syncthreads();

    // 48 output elements per block: (local seg s in 0..2) x (feature m in 0..15).
    // Sum the 40 row-groups with rg % 3 == s.
    if (t < 48) {
        const int s = t >> 4;    // 0..2
        const int m = t & 15;    // 0..15
        const float* sf = reinterpret_cast<const float*>(smem);  // RG*16 floats
        float sum = 0.f;
        #pragma unroll
        for (int k = 0; k < RG / 3; ++k) {
            sum += sf[(s + 3 * k) * 16 + m];
        }
        const float scale = (s == 0) ? (1.0f / 334.0f) : (1.0f / 333.0f);
        out[(size_t)seq * 96 + (size_t)(half * 3 + s) * 16 + m] = sum * scale;
    }
}

extern "C" void kernel_launch(void* const* d_in, const int* in_sizes, int n_in,
                              void* d_out, int out_size) {
    const float* in = (const float*)d_in[0];
    float* out = (float*)d_out;
    seg_mean_kernel<<<4096, THREADS>>>(in, out);
}